// round 17
// baseline (speedup 1.0000x reference)
#include <cuda_runtime.h>
#include <cuda_bf16.h>
#include <cstdint>

// Problem constants (fixed by dataset)
#define BB    256      // batch
#define TT    1024     // timesteps
#define DX    64       // obs dim
#define DZ    256      // latent dim
#define DH    1024     // hidden dim
#define SS    16       // subjects
#define DF    64       // teacher-forced dims
#define ALPHA 0.2f
#define GRP   4        // batches per work item
#define NIT   76       // max work items: sum ceil(n_s/4) <= (256+3*16)/4 = 76

// -------- static device scratch (no allocation allowed) --------
__device__ float g_P64[DX * DF];                    // pinv(obs)[:, :64]  (64x64)
__device__ float g_forcing[(size_t)BB * TT * DF];   // 64 MB
__device__ float g_Z[(size_t)BB * TT * DZ];         // 256 MB latent trajectory
__device__ int   g_order[BB];
__device__ int4  g_work[NIT];                       // (subject, start, cnt, 0)

__device__ __forceinline__ float dot4(float4 a, float4 b) {
    return fmaf(a.x, b.x, fmaf(a.y, b.y, fmaf(a.z, b.z, a.w * b.w)));
}
__device__ __forceinline__ uint32_t smem_u32(const void* p) {
    uint32_t a;
    asm("{ .reg .u64 t; cvta.to.shared.u64 t, %1; cvt.u32.u64 %0, t; }" : "=r"(a) : "l"(p));
    return a;
}
__device__ __forceinline__ uint32_t mapa_u32(uint32_t a, uint32_t r) {
    uint32_t d;
    asm("mapa.shared::cluster.u32 %0, %1, %2;" : "=r"(d) : "r"(a), "r"(r));
    return d;
}
__device__ __forceinline__ void st_cluster4(uint32_t a, float4 v) {
    asm volatile("st.shared::cluster.v4.f32 [%0], {%1,%2,%3,%4};"
                 :: "r"(a), "f"(v.x), "f"(v.y), "f"(v.z), "f"(v.w) : "memory");
}
#define CLUSTER_SYNC_() do { \
    asm volatile("barrier.cluster.arrive.aligned;" ::: "memory"); \
    asm volatile("barrier.cluster.wait.aligned;"   ::: "memory"); \
} while (0)

// ===================== Kernel A: pinv via normal equations =====================
__global__ void kpinv(const float* __restrict__ obs) {
    __shared__ float Gs[64 * 64];
    __shared__ float Au[64 * 64];
    __shared__ float fcol[64];
    __shared__ float s_piv;
    int tid = threadIdx.x;   // 256 threads

    for (int e = tid; e < 4096; e += 256) {
        int a = e >> 6, b = e & 63;
        float s = 0.f;
        for (int r = 0; r < DZ; ++r)
            s += obs[r * DX + a] * obs[r * DX + b];
        Gs[e] = s;
        Au[e] = (a == b) ? 1.f : 0.f;
    }
    __syncthreads();

    for (int c = 0; c < 64; ++c) {
        if (tid == 0) s_piv = 1.f / Gs[c * 64 + c];
        __syncthreads();
        if (tid < 128) {
            if (tid < 64) Gs[c * 64 + tid] *= s_piv;
            else          Au[c * 64 + (tid - 64)] *= s_piv;
        }
        __syncthreads();
        if (tid < 64) fcol[tid] = (tid == c) ? 0.f : Gs[tid * 64 + c];
        __syncthreads();
        for (int idx = tid; idx < 8192; idx += 256) {
            int r = idx >> 7, col = idx & 127;
            float f = fcol[r];
            if (f != 0.f) {
                if (col < 64) Gs[r * 64 + col]        -= f * Gs[c * 64 + col];
                else          Au[r * 64 + (col - 64)] -= f * Au[c * 64 + (col - 64)];
            }
        }
        __syncthreads();
    }

    for (int e = tid; e < 64 * DF; e += 256) {
        int i = e >> 6, j = e & 63;
        float s = 0.f;
        for (int k = 0; k < 64; ++k)
            s += Au[i * 64 + k] * obs[j * DX + k];
        g_P64[i * DF + j] = s;
    }
}

// ===================== Kernel B: forcing[:, :, :64] = x @ P64 =====================
__global__ void kforce(const float* __restrict__ x) {
    __shared__ float Ps[64 * 64];
    __shared__ float xs[4 * 64];
    int tid = threadIdx.x;  // 256
    for (int idx = tid; idx < 4096; idx += 256) Ps[idx] = g_P64[idx];
    int rr = tid >> 6, j = tid & 63;
    for (int it = 0; it < 4; ++it) {
        size_t r0 = (size_t)blockIdx.x * 16 + it * 4;
        __syncthreads();
        xs[tid] = x[r0 * DX + tid];
        __syncthreads();
        float acc = 0.f;
        #pragma unroll
        for (int i = 0; i < 64; ++i)
            acc += xs[rr * 64 + i] * Ps[i * 64 + j];
        g_forcing[(r0 + rr) * DF + j] = acc;
    }
}

// ===================== Kernel C: deterministic subject grouping (GRP=4) =====================
__global__ void kgroup(const int* __restrict__ subject) {
    __shared__ int cnts[SS], base[SS];
    int tid = threadIdx.x;   // 256
    int s = subject[tid];
    if (tid < SS) {
        int c = 0;
        for (int b = 0; b < BB; ++b) c += (subject[b] == tid);
        cnts[tid] = c;
    }
    __syncthreads();
    if (tid == 0) {
        int acc = 0;
        for (int i = 0; i < SS; ++i) { base[i] = acc; acc += cnts[i]; }
    }
    __syncthreads();
    int rank = 0;
    for (int b = 0; b < tid; ++b) rank += (subject[b] == s);
    g_order[base[s] + rank] = tid;
    if (tid == 0) {
        int w = 0;
        for (int s2 = 0; s2 < SS; ++s2) {
            int n = cnts[s2];
            for (int c0 = 0; c0 < n; c0 += GRP) {
                int c = n - c0; if (c > GRP) c = GRP;
                g_work[w] = make_int4(s2, base[s2] + c0, c, 0);
                ++w;
            }
        }
        for (; w < NIT; ++w) g_work[w] = make_int4(0, 0, 0, 0);
    }
}

// ===================== Kernel R: recurrence, cluster-2, partial-z exchange =====
// Rank r owns h-half [512r, 512r+512). Phase 1 computes hid for the own half
// only (stored locally, NO exchange). Phase 2 computes partial z-sums for ALL
// 256 i over the own h-half; only the 4KB partial block is sent to the peer.
// Both CTAs then combine redundantly -> full z everywhere, ONE cluster barrier
// per step. Phase-1 weights prefetched one pass ahead (explicit registers).
__global__ void __launch_bounds__(1024, 1) __cluster_dims__(2, 1, 1)
krecur(const float* __restrict__ A_t,  const float* __restrict__ h1_t,
       const float* __restrict__ h2_t,
       const float* __restrict__ W1_t, const float* __restrict__ W2_t) {
    __shared__ float zs[GRP][DZ];
    __shared__ float hidl[GRP][DH / 2];      // own h-half only
    __shared__ float part_own[GRP][DZ];
    __shared__ float part_peer[GRP][DZ];
    __shared__ float As[DZ], h1s[DZ], h2s[DH];
    __shared__ int sb[GRP];

    int item = blockIdx.x >> 1;
    uint32_t rank;
    asm("mov.u32 %0, %%cluster_ctarank;" : "=r"(rank));

    int4 wk = g_work[item];
    int cnt = wk.z;
    if (cnt == 0) return;                 // both CTAs of the cluster exit together
    int s = wk.x;
    int tid = threadIdx.x;                // 1024
    int w = tid >> 5, l = tid & 31;

    if (tid < GRP) sb[tid] = g_order[wk.y + ((tid < cnt) ? tid : cnt - 1)];
    if (tid < DZ) {
        As[tid]  = A_t[s * DZ + tid];
        h1s[tid] = h1_t[s * DZ + tid];
        zs[0][tid] = 0.f; zs[1][tid] = 0.f; zs[2][tid] = 0.f; zs[3][tid] = 0.f;
    }
    h2s[tid] = h2_t[s * DH + tid];
    __syncthreads();

    const float4* w2v = (const float4*)(W2_t + (size_t)s * DH * DZ);  // row h = 64 float4
    const float4* w1v = (const float4*)(W1_t + (size_t)s * DZ * DH);  // row i = 256 float4

    const uint32_t peer   = rank ^ 1u;
    const uint32_t part_r = mapa_u32(smem_u32(part_peer), peer);  // peer's part_peer

    const int hbase = (int)rank * 512;    // own h-half base (global h index)

    for (int t = 0; t < TT; ++t) {
        // ---- generalized teacher forcing on first DF dims (both CTAs, identical) ----
        // t==0: z0[:DF]=f0, then a*f0+(1-a)*f0 = f0 -> write f0 directly.
        if (tid < GRP * DF) {
            int j = tid >> 6, d = tid & 63;
            float fv = g_forcing[((size_t)sb[j] * TT + t) * DF + d];
            zs[j][d] = (t == 0) ? fv : (ALPHA * fv + (1.f - ALPHA) * zs[j][d]);
        }
        __syncthreads();

        // cache all 4 z batches in registers for phase 1
        float4 z0a = *(const float4*)&zs[0][4 * l];
        float4 z0b = *(const float4*)&zs[0][128 + 4 * l];
        float4 z1a = *(const float4*)&zs[1][4 * l];
        float4 z1b = *(const float4*)&zs[1][128 + 4 * l];
        float4 z2a = *(const float4*)&zs[2][4 * l];
        float4 z2b = *(const float4*)&zs[2][128 + 4 * l];
        float4 z3a = *(const float4*)&zs[3][4 * l];
        float4 z3b = *(const float4*)&zs[3][128 + 4 * l];

        // ---- phase 1: hidl[b][hl] = relu( sum_k W2[hbase+hl][k]*z[b][k] + h2 ) ----
        // explicit depth-1 prefetch of the next pass's weight row
        {
            const float4* row0 = w2v + (size_t)(hbase + w) * 64;
            float4 ca = row0[l], cb = row0[32 + l];
            #pragma unroll
            for (int p = 0; p < 16; ++p) {
                int pn = (p < 15) ? p + 1 : 15;
                const float4* rown = w2v + (size_t)(hbase + pn * 32 + w) * 64;
                float4 na = rown[l], nb = rown[32 + l];
                float a0 = dot4(ca, z0a) + dot4(cb, z0b);
                float a1 = dot4(ca, z1a) + dot4(cb, z1b);
                float a2 = dot4(ca, z2a) + dot4(cb, z2b);
                float a3 = dot4(ca, z3a) + dot4(cb, z3b);
                // pair reduces: lanes 0 -> (b0,b2), 16 -> (b1,b3)
                float r01 = ((l & 16) ? a1 : a0) + __shfl_xor_sync(0xffffffffu, (l & 16) ? a0 : a1, 16);
                float r23 = ((l & 16) ? a3 : a2) + __shfl_xor_sync(0xffffffffu, (l & 16) ? a2 : a3, 16);
                #pragma unroll
                for (int d = 8; d >= 1; d >>= 1) {
                    r01 += __shfl_xor_sync(0xffffffffu, r01, d);
                    r23 += __shfl_xor_sync(0xffffffffu, r23, d);
                }
                int hl = p * 32 + w;                  // local h in [0,512)
                float hb = h2s[hbase + hl];
                if (l == 0) {
                    hidl[0][hl] = fmaxf(r01 + hb, 0.f);
                    hidl[2][hl] = fmaxf(r23 + hb, 0.f);
                } else if (l == 16) {
                    hidl[1][hl] = fmaxf(r01 + hb, 0.f);
                    hidl[3][hl] = fmaxf(r23 + hb, 0.f);
                }
                ca = na; cb = nb;
            }
        }
        __syncthreads();

        // ---- phase 2: part_own[b][i] = sum_{h in own half} W1[i][h]*hid[b][h] ----
        // warp w covers rows i = 8w + 4*pass + r; hid chunks loaded once per c,
        // shared across the 4 rows of the pass.
        #pragma unroll
        for (int pass = 0; pass < 2; ++pass) {
            float acc[4][4];   // [row r][batch b]
            #pragma unroll
            for (int r = 0; r < 4; ++r)
                #pragma unroll
                for (int b = 0; b < 4; ++b) acc[r][b] = 0.f;
            #pragma unroll
            for (int c = 0; c < 4; ++c) {
                float4 hc0 = *(const float4*)&hidl[0][c * 128 + 4 * l];
                float4 hc1 = *(const float4*)&hidl[1][c * 128 + 4 * l];
                float4 hc2 = *(const float4*)&hidl[2][c * 128 + 4 * l];
                float4 hc3 = *(const float4*)&hidl[3][c * 128 + 4 * l];
                #pragma unroll
                for (int r = 0; r < 4; ++r) {
                    int i = 8 * w + 4 * pass + r;
                    float4 wv = w1v[(size_t)i * 256 + (int)rank * 128 + c * 32 + l];
                    acc[r][0] += dot4(wv, hc0);
                    acc[r][1] += dot4(wv, hc1);
                    acc[r][2] += dot4(wv, hc2);
                    acc[r][3] += dot4(wv, hc3);
                }
            }
            #pragma unroll
            for (int r = 0; r < 4; ++r) {
                int i = 8 * w + 4 * pass + r;
                float a0 = acc[r][0], a1 = acc[r][1], a2 = acc[r][2], a3 = acc[r][3];
                float r01 = ((l & 16) ? a1 : a0) + __shfl_xor_sync(0xffffffffu, (l & 16) ? a0 : a1, 16);
                float r23 = ((l & 16) ? a3 : a2) + __shfl_xor_sync(0xffffffffu, (l & 16) ? a2 : a3, 16);
                #pragma unroll
                for (int d = 8; d >= 1; d >>= 1) {
                    r01 += __shfl_xor_sync(0xffffffffu, r01, d);
                    r23 += __shfl_xor_sync(0xffffffffu, r23, d);
                }
                if (l == 0) {
                    part_own[0][i] = r01;
                    part_own[2][i] = r23;
                } else if (l == 16) {
                    part_own[1][i] = r01;
                    part_own[3][i] = r23;
                }
            }
        }
        __syncthreads();

        // ---- exchange partials: 4KB -> peer's part_peer buffer ----
        if (tid < 256) {
            int b = tid >> 6, i0 = (tid & 63) * 4;
            float4 v = *(const float4*)&part_own[b][i0];
            st_cluster4(part_r + (uint32_t)(b * DZ + i0) * 4u, v);
        }
        CLUSTER_SYNC_();   // the single cluster barrier per step

        // ---- combine (redundant on both CTAs): z = A*z + own + peer + h1 ----
        {
            int b = tid >> 8, i = tid & 255;
            float zn = fmaf(As[i], zs[b][i], part_own[b][i] + part_peer[b][i] + h1s[i]);
            zs[b][i] = zn;
            // rank stores its own i-half (coalesced scalar stores)
            if (b < cnt && (i >> 7) == (int)rank)
                g_Z[((size_t)sb[b] * TT + t) * DZ + i] = zn;
        }
        __syncthreads();   // zs ready for next step's TF
    }
}

// ===================== Kernel D: decode out = Z @ obs =====================
__global__ void kdecode(const float* __restrict__ obs, float* __restrict__ out) {
    extern __shared__ float smd[];
    float* obss = smd;               // DZ*64 = 16384 floats (64 KB)
    float* zsm  = obss + DZ * 64;    // 32*DZ =  8192 floats (32 KB)
    int tid = threadIdx.x;           // 512
    for (int idx = tid; idx < DZ * 64; idx += 512) obss[idx] = obs[idx];
    int g = tid & 15, j = tid >> 4;  // 16 x-groups of 4, 32 rows
    int x0 = g * 4;
    for (int it = 0; it < 4; ++it) {
        size_t r0 = (size_t)blockIdx.x * 128 + it * 32;
        __syncthreads();
        for (int idx = tid; idx < 32 * DZ; idx += 512) zsm[idx] = g_Z[r0 * DZ + idx];
        __syncthreads();
        float4 acc = {0, 0, 0, 0};
        const float* zp = zsm + j * DZ;
        #pragma unroll 4
        for (int zi = 0; zi < DZ; ++zi) {
            float zv = zp[zi];
            float4 ov = *(const float4*)&obss[zi * 64 + x0];
            acc.x += zv * ov.x; acc.y += zv * ov.y; acc.z += zv * ov.z; acc.w += zv * ov.w;
        }
        *(float4*)&out[(r0 + j) * 64 + x0] = acc;
    }
}

// ===================== host =====================
extern "C" void kernel_launch(void* const* d_in, const int* in_sizes, int n_in,
                              void* d_out, int out_size) {
    const float* x_gt  = (const float*)d_in[0];   // (256,1024,64)
    const int*   subj  = (const int*)  d_in[1];   // (256,)
    const float* obs   = (const float*)d_in[2];   // (256,64)
    const float* A_t   = (const float*)d_in[3];   // (16,256)
    const float* W1_t  = (const float*)d_in[4];   // (16,256,1024)
    const float* W2_t  = (const float*)d_in[5];   // (16,1024,256)
    const float* h1_t  = (const float*)d_in[6];   // (16,256)
    const float* h2_t  = (const float*)d_in[7];   // (16,1024)
    float* out = (float*)d_out;

    cudaFuncSetAttribute(kdecode, cudaFuncAttributeMaxDynamicSharedMemorySize, 98304);

    kpinv<<<1, 256>>>(obs);
    kforce<<<(BB * TT) / 16, 256>>>(x_gt);
    kgroup<<<1, 256>>>(subj);
    krecur<<<2 * NIT, 1024>>>(A_t, h1_t, h2_t, W1_t, W2_t);   // 76 clusters of 2 CTAs
    kdecode<<<(BB * TT) / 128, 512, 98304>>>(obs, out);
}